// round 13
// baseline (speedup 1.0000x reference)
#include <cuda_runtime.h>
#include <math.h>
#include <stdint.h>

#define NBATCH 64
#define NSTEP  1024
#define NIN    256
#define NH     512

// smem floats: wsm [3][32][512] swizzled | hsm [2][4][512] | part [8][384] | done[32]
#define WS_OFF   0
#define HS_OFF   (3*32*512)                 // 49152
#define PT_OFF   (HS_OFF + 2*4*512)         // 53248
#define DONE_OFF (PT_OFF + 8*384)           // 56320
#define SMEM_FLOATS (DONE_OFF + 32)
#define SMEM_BYTES  (SMEM_FLOATS*4)         // 225,408 B

typedef unsigned long long u64;

#define FMA2(acc, a, b) asm("fma.rn.f32x2 %0, %1, %2, %0;" : "+l"(acc) : "l"(a), "l"(b))
#define DUP2(r, x)      asm("mov.b64 %0, {%1, %1};" : "=l"(r) : "f"(x))
#define UNPACK2(lo, hi, v) asm("mov.b64 {%0, %1}, %2;" : "=f"(lo), "=f"(hi) : "l"(v))

__device__ float    g_x[(size_t)3*NBATCH*NSTEP*NH];   // input projections
__device__ float    g_h[2*NBATCH*NH];
__device__ unsigned g_flags[256];                      // [16 groups][16 jt]

__device__ __forceinline__ unsigned ld_acq(const unsigned* p) {
  unsigned v;
  asm volatile("ld.global.acquire.gpu.b32 %0, [%1];" : "=r"(v) : "l"(p) : "memory");
  return v;
}
__device__ __forceinline__ void st_rel(unsigned* p, unsigned v) {
  asm volatile("st.global.release.gpu.b32 [%0], %1;" :: "l"(p), "r"(v) : "memory");
}
__device__ __forceinline__ unsigned ld_acq_sh(const unsigned* p) {
  unsigned v;
  asm volatile("ld.acquire.cta.b32 %0, [%1];" : "=r"(v) : "l"(p) : "memory");
  return v;
}
__device__ __forceinline__ void st_rel_sh(unsigned* p, unsigned v) {
  asm volatile("st.release.cta.b32 [%0], %1;" :: "l"(p), "r"(v) : "memory");
}

// ---------------- input projection GEMM ----------------
__global__ void __launch_bounds__(256) xproj_kernel(
    const float* __restrict__ A,
    const float* __restrict__ w0, const float* __restrict__ w1, const float* __restrict__ w2,
    const float* __restrict__ b0, const float* __restrict__ b1, const float* __restrict__ b2)
{
  __shared__ float As[32][68];
  __shared__ float Bs[32][68];

  int tid = threadIdx.x;
  if (blockIdx.x == 0 && blockIdx.y == 0 && blockIdx.z == 0)
    g_flags[tid] = 0u;

  int g = blockIdx.z;
  const float* W    = (g==0) ? w0 : ((g==1) ? w1 : w2);
  const float* bias = (g==0) ? b0 : ((g==1) ? b1 : b2);
  float* C = g_x + (size_t)g * (size_t)(NBATCH*NSTEP) * NH;

  int m0 = blockIdx.y * 64;
  int n0 = blockIdx.x * 64;
  int tx = tid & 15, ty = tid >> 4;
  int lr = tid >> 3;
  int lc = (tid & 7) * 4;

  u64 acc2[4][2] = {};

  for (int k0 = 0; k0 < NIN; k0 += 32) {
    float4 a0 = *(const float4*)(A + (size_t)(m0+lr   )*NIN + k0 + lc);
    float4 a1 = *(const float4*)(A + (size_t)(m0+lr+32)*NIN + k0 + lc);
    float4 v0 = *(const float4*)(W + (size_t)(n0+lr   )*NIN + k0 + lc);
    float4 v1 = *(const float4*)(W + (size_t)(n0+lr+32)*NIN + k0 + lc);
    __syncthreads();
    As[lc+0][lr] = a0.x; As[lc+1][lr] = a0.y; As[lc+2][lr] = a0.z; As[lc+3][lr] = a0.w;
    As[lc+0][lr+32] = a1.x; As[lc+1][lr+32] = a1.y; As[lc+2][lr+32] = a1.z; As[lc+3][lr+32] = a1.w;
    Bs[lc+0][lr] = v0.x; Bs[lc+1][lr] = v0.y; Bs[lc+2][lr] = v0.z; Bs[lc+3][lr] = v0.w;
    Bs[lc+0][lr+32] = v1.x; Bs[lc+1][lr+32] = v1.y; Bs[lc+2][lr+32] = v1.z; Bs[lc+3][lr+32] = v1.w;
    __syncthreads();
    #pragma unroll
    for (int kk = 0; kk < 32; kk++) {
      float4 av = *(const float4*)(&As[kk][ty*4]);
      ulonglong2 bp = *(const ulonglong2*)(&Bs[kk][tx*4]);
      u64 d0, d1, d2, d3;
      DUP2(d0, av.x); DUP2(d1, av.y); DUP2(d2, av.z); DUP2(d3, av.w);
      FMA2(acc2[0][0], d0, bp.x); FMA2(acc2[0][1], d0, bp.y);
      FMA2(acc2[1][0], d1, bp.x); FMA2(acc2[1][1], d1, bp.y);
      FMA2(acc2[2][0], d2, bp.x); FMA2(acc2[2][1], d2, bp.y);
      FMA2(acc2[3][0], d3, bp.x); FMA2(acc2[3][1], d3, bp.y);
    }
  }

  float4 bv = *(const float4*)(bias + n0 + tx*4);
  #pragma unroll
  for (int i = 0; i < 4; i++) {
    int row = m0 + ty*4 + i;
    float c0, c1, c2, c3;
    UNPACK2(c0, c1, acc2[i][0]);
    UNPACK2(c2, c3, acc2[i][1]);
    float4 o;
    o.x = c0 + bv.x; o.y = c1 + bv.y;
    o.z = c2 + bv.z; o.w = c3 + bv.w;
    *(float4*)(C + (size_t)row*NH + n0 + tx*4) = o;
  }
}

// ------------- persistent GRU recurrence: 2 chains, FUSED weight pass -------------
// 128 CTAs = 16 j-tiles x 8 CTA-rows (m). CTA (m, jt) runs chains gA=2m, gB=2m+1
// (4 batches each) over cols [jt*32,+32). The matvec loads each weight vector ONCE
// and FMAs into both chains' accumulators (8 batches), halving weight smem traffic.
// Epilogues remain split: reduce+release chain A first (early release), then chain B
// reusing the same part buffer. Warp r waits on both chains' chunk-r done flags.
// 544 threads: warps 0..15 workers (k-split 16), warp 16 = L2 flag poller.
__global__ void __launch_bounds__(544, 1) gru_rec(
    const float* __restrict__ h0,
    const float* __restrict__ w_hr, const float* __restrict__ w_hz, const float* __restrict__ w_hn,
    const float* __restrict__ b_hr, const float* __restrict__ b_hz, const float* __restrict__ b_hn,
    float* __restrict__ out, int write_hlast)
{
  extern __shared__ float sm[];
  float* wsm  = sm + WS_OFF;                 // [3][32][512], float4-XOR swizzled
  float* hsm  = sm + HS_OFF;                 // [2 chains][4][512]
  float* part = sm + PT_OFF;                 // [8][384]
  unsigned* done = (unsigned*)(sm + DONE_OFF);  // [32] = [2 chains][16]

  int tid  = threadIdx.x;
  int r    = tid >> 5;                 // 0..15 worker k-split; 16 = poller
  int jl   = tid & 31;
  int m    = blockIdx.x >> 4;          // 0..7
  int jt   = blockIdx.x & 15;
  int j    = jt*32 + jl;
  int k0   = r*32;
  int sw   = (jl & 7);                 // float4 swizzle key

  if (tid < 512) {
    const float* srcs[3] = {w_hr, w_hz, w_hn};
    #pragma unroll
    for (int g = 0; g < 3; g++) {
      const float* wsrc = srcs[g] + (size_t)j*NH;
      float* wdst = wsm + (g*32 + jl)*512;
      #pragma unroll
      for (int kk = 0; kk < 32; kk += 4) {
        int k16 = (k0 + kk) >> 2;
        *(float4*)(wdst + ((k16 ^ sw) << 2)) = *(const float4*)(wsrc + k0 + kk);
      }
    }
  }
  if (tid < 32) done[tid] = 0u;
  __syncthreads();

  // ---- poller warp: 32 lanes <-> 32 flags (this CTA-row's two groups) ----
  if (r == 16) {
    if (jl < 32) {
      const unsigned* fp = g_flags + m*32 + jl;
      unsigned* dp = done + jl;
      unsigned last = 0u;
      while (last < (unsigned)NSTEP) {
        unsigned v = ld_acq(fp);
        if (v > last) { last = v; st_rel_sh(dp, v); }
        else __nanosleep(40);
      }
    }
    return;
  }

  // ---- workers ----
  float bhr = b_hr[j], bhz = b_hz[j], bhn = b_hn[j];

  const float* wr = wsm + (0*32 + jl)*512;
  const float* wz = wsm + (1*32 + jl)*512;
  const float* wn = wsm + (2*32 + jl)*512;

  int eb = tid >> 5;                   // 0..3 for epilogue threads (tid<128)
  float hprev[2];
  const float* xp[2][3];
  float* outp[2];
  float* hlastp[2];
  unsigned* flagp[2];
  #pragma unroll
  for (int c = 0; c < 2; c++) {
    int bb = (2*m + c)*4 + eb;
    hprev[c] = (tid < 128) ? h0[(size_t)bb*NH + j] : 0.f;
    xp[c][0] = g_x + (size_t)bb*NSTEP*NH + j;
    xp[c][1] = xp[c][0] + (size_t)NBATCH*NSTEP*NH;
    xp[c][2] = xp[c][1] + (size_t)NBATCH*NSTEP*NH;
    outp[c]  = out + (size_t)bb*NSTEP*NH + j;
    hlastp[c] = out + (size_t)NBATCH*NSTEP*NH + (size_t)bb*NH + j;
    flagp[c] = g_flags + m*32 + c*16 + jt;
  }

  // staging map: warp r stages chunk h[4b][k0..+32) = 32 float4, 1 per lane (per chain)
  int sb = jl >> 3, sc = jl & 7;
  int sidx = sb*128 + r*8 + sc;
  const unsigned* dpa = done + r;       // chain A chunk-r flag
  const unsigned* dpb = done + 16 + r;  // chain B chunk-r flag

  #pragma unroll 1
  for (int t = 0; t < NSTEP; t++) {
    // prefetch both chains' x contributions
    float xv[2][3];
    if (tid < 128) {
      #pragma unroll
      for (int c = 0; c < 2; c++) {
        xv[c][0] = __ldcs(xp[c][0] + (size_t)t*NH);
        xv[c][1] = __ldcs(xp[c][1] + (size_t)t*NH);
        xv[c][2] = __ldcs(xp[c][2] + (size_t)t*NH);
      }
    }

    // wait: both chains' chunk-r producers must have finished step t-1
    if (t > 0) {
      while (ld_acq_sh(dpa) < (unsigned)t) __nanosleep(20);
      while (ld_acq_sh(dpb) < (unsigned)t) __nanosleep(20);
    }

    // stage both chains' chunks (independent -> overlapped)
    {
      const float4* srcA;
      const float4* srcB;
      if (t == 0) {
        srcA = (const float4*)(h0 + (size_t)(2*m + 0)*4*NH);
        srcB = (const float4*)(h0 + (size_t)(2*m + 1)*4*NH);
      } else {
        const float* base = g_h + (size_t)((t-1)&1)*NBATCH*NH;
        srcA = (const float4*)(base + (size_t)(2*m + 0)*4*NH);
        srcB = (const float4*)(base + (size_t)(2*m + 1)*4*NH);
      }
      ((float4*)hsm)[sidx]        = __ldcg(srcA + sidx);
      ((float4*)hsm)[512 + sidx]  = __ldcg(srcB + sidx);
    }
    __syncwarp();

    // FUSED matvec: one weight pass, 8 batches (4 per chain), 3 gates, fp32x2
    u64 ar2[8] = {}, az2[8] = {}, an2[8] = {};
    #pragma unroll
    for (int kk8 = 0; kk8 < 8; kk8++) {
      int s4 = ((r*8 + kk8) ^ sw) << 2;
      int k  = k0 + kk8*4;
      ulonglong2 vr = *(const ulonglong2*)(wr + s4);
      ulonglong2 vz = *(const ulonglong2*)(wz + s4);
      ulonglong2 vn = *(const ulonglong2*)(wn + s4);
      #pragma unroll
      for (int b = 0; b < 8; b++) {
        const float* hb = hsm + ((b < 4) ? (b*NH) : (2048 + (b-4)*NH)) + k;
        ulonglong2 hv = *(const ulonglong2*)hb;
        FMA2(ar2[b], vr.x, hv.x); FMA2(ar2[b], vr.y, hv.y);
        FMA2(az2[b], vz.x, hv.x); FMA2(az2[b], vz.y, hv.y);
        FMA2(an2[b], vn.x, hv.x); FMA2(an2[b], vn.y, hv.y);
      }
    }
    float sr[8], sz[8], sn[8];
    #pragma unroll
    for (int b = 0; b < 8; b++) {
      float lo, hi;
      UNPACK2(lo, hi, ar2[b]); sr[b] = lo + hi;
      UNPACK2(lo, hi, az2[b]); sz[b] = lo + hi;
      UNPACK2(lo, hi, an2[b]); sn[b] = lo + hi;
    }

    // ---- two reduce/epilogue sub-phases sharing the part buffer ----
    #pragma unroll
    for (int c = 0; c < 2; c++) {
      int bo = c*4;
      // part free (prev phase / prev step epilogue finished reading)
      asm volatile("bar.sync 1, 512;" ::: "memory");

      if (r >= 8) {
        int row = (r - 8)*384;
        #pragma unroll
        for (int b = 0; b < 4; b++) {
          part[row +   0 + b*32 + jl] = sr[bo + b];
          part[row + 128 + b*32 + jl] = sz[bo + b];
          part[row + 256 + b*32 + jl] = sn[bo + b];
        }
      }
      asm volatile("bar.sync 1, 512;" ::: "memory");

      if (r < 8) {
        int row = r*384;
        #pragma unroll
        for (int b = 0; b < 4; b++) {
          part[row +   0 + b*32 + jl] += sr[bo + b];
          part[row + 128 + b*32 + jl] += sz[bo + b];
          part[row + 256 + b*32 + jl] += sn[bo + b];
        }
      }
      asm volatile("bar.sync 1, 512;" ::: "memory");

      if (tid < 128) {
        float Sr = 0.f, Sz = 0.f, Sn = 0.f;
        #pragma unroll
        for (int rr = 0; rr < 8; rr++) {
          Sr += part[rr*384 +       tid];
          Sz += part[rr*384 + 128 + tid];
          Sn += part[rr*384 + 256 + tid];
        }
        float rg = 1.f/(1.f + __expf(-(xv[c][0] + Sr + bhr)));
        float zg = 1.f/(1.f + __expf(-(xv[c][1] + Sz + bhz)));
        float ng = tanhf(xv[c][2] + rg*(Sn + bhn));
        float hnew = (1.f - zg)*ng + zg*hprev[c];
        hprev[c] = hnew;

        int bb = (2*m + c)*4 + eb;
        __stcg(&g_h[(size_t)(t&1)*NBATCH*NH + (size_t)bb*NH + j], hnew);

        asm volatile("bar.sync 2, 128;" ::: "memory");
        if (tid == 0) {
          st_rel(flagp[c], (unsigned)(t+1));
          st_rel_sh(done + c*16 + jt, (unsigned)(t+1));
        }

        __stcs(outp[c] + (size_t)t*NH, hnew);
        if (write_hlast && t == NSTEP-1) hlastp[c][0] = hnew;
      }
    }
  }
}

extern "C" void kernel_launch(void* const* d_in, const int* in_sizes, int n_in,
                              void* d_out, int out_size) {
  const float* inp  = (const float*)d_in[0];
  const float* h0   = (const float*)d_in[1];
  const float* w_ir = (const float*)d_in[2];
  const float* w_iz = (const float*)d_in[3];
  const float* w_in = (const float*)d_in[4];
  const float* b_ir = (const float*)d_in[5];
  const float* b_iz = (const float*)d_in[6];
  const float* b_in = (const float*)d_in[7];
  const float* w_hr = (const float*)d_in[8];
  const float* w_hz = (const float*)d_in[9];
  const float* w_hn = (const float*)d_in[10];
  const float* b_hr = (const float*)d_in[11];
  const float* b_hz = (const float*)d_in[12];
  const float* b_hn = (const float*)d_in[13];
  float* out = (float*)d_out;

  cudaFuncSetAttribute(gru_rec, cudaFuncAttributeMaxDynamicSharedMemorySize, SMEM_BYTES);

  dim3 gg(NH/64, (NBATCH*NSTEP)/64, 3);
  xproj_kernel<<<gg, 256>>>(inp, w_ir, w_iz, w_in, b_ir, b_iz, b_in);

  int write_hlast = (out_size >= NBATCH*NSTEP*NH + NBATCH*NH) ? 1 : 0;
  gru_rec<<<128, 544, SMEM_BYTES>>>(h0, w_hr, w_hz, w_hn, b_hr, b_hz, b_hn,
                                    out, write_hlast);
}

// round 14
// speedup vs baseline: 1.3141x; 1.3141x over previous
#include <cuda_runtime.h>
#include <math.h>
#include <stdint.h>

#define NBATCH 64
#define NSTEP  1024
#define NIN    256
#define NH     512

// smem floats: wsm [3][32][512] swizzled | hsm [4][512] | part [16][384] | done[32]
#define WS_OFF   0
#define HS_OFF   (3*32*512)                 // 49152
#define PT_OFF   (HS_OFF + 4*512)           // 51200
#define DONE_OFF (PT_OFF + 16*384)          // 57344
#define SMEM_FLOATS (DONE_OFF + 32)
#define SMEM_BYTES  (SMEM_FLOATS*4)         // 229,504 B

typedef unsigned long long u64;

#define FMA2(acc, a, b) asm("fma.rn.f32x2 %0, %1, %2, %0;" : "+l"(acc) : "l"(a), "l"(b))
#define DUP2(r, x)      asm("mov.b64 %0, {%1, %1};" : "=l"(r) : "f"(x))
#define UNPACK2(lo, hi, v) asm("mov.b64 {%0, %1}, %2;" : "=f"(lo), "=f"(hi) : "l"(v))

__device__ float    g_x[(size_t)3*NBATCH*NSTEP*NH];   // input projections
__device__ float    g_h[2*NBATCH*NH];
__device__ unsigned g_flags[256];                      // [16 groups][16 jt]

__device__ __forceinline__ unsigned ld_acq(const unsigned* p) {
  unsigned v;
  asm volatile("ld.global.acquire.gpu.b32 %0, [%1];" : "=r"(v) : "l"(p) : "memory");
  return v;
}
__device__ __forceinline__ void st_rel(unsigned* p, unsigned v) {
  asm volatile("st.global.release.gpu.b32 [%0], %1;" :: "l"(p), "r"(v) : "memory");
}
__device__ __forceinline__ unsigned ld_acq_sh(const unsigned* p) {
  unsigned v;
  asm volatile("ld.acquire.cta.b32 %0, [%1];" : "=r"(v) : "l"(p) : "memory");
  return v;
}
__device__ __forceinline__ void st_rel_sh(unsigned* p, unsigned v) {
  asm volatile("st.release.cta.b32 [%0], %1;" :: "l"(p), "r"(v) : "memory");
}

// ---------------- input projection GEMM ----------------
__global__ void __launch_bounds__(256) xproj_kernel(
    const float* __restrict__ A,
    const float* __restrict__ w0, const float* __restrict__ w1, const float* __restrict__ w2,
    const float* __restrict__ b0, const float* __restrict__ b1, const float* __restrict__ b2)
{
  __shared__ float As[32][68];
  __shared__ float Bs[32][68];

  int tid = threadIdx.x;
  if (blockIdx.x == 0 && blockIdx.y == 0 && blockIdx.z == 0)
    g_flags[tid] = 0u;

  int g = blockIdx.z;
  const float* W    = (g==0) ? w0 : ((g==1) ? w1 : w2);
  const float* bias = (g==0) ? b0 : ((g==1) ? b1 : b2);
  float* C = g_x + (size_t)g * (size_t)(NBATCH*NSTEP) * NH;

  int m0 = blockIdx.y * 64;
  int n0 = blockIdx.x * 64;
  int tx = tid & 15, ty = tid >> 4;
  int lr = tid >> 3;
  int lc = (tid & 7) * 4;

  u64 acc2[4][2] = {};

  for (int k0 = 0; k0 < NIN; k0 += 32) {
    float4 a0 = *(const float4*)(A + (size_t)(m0+lr   )*NIN + k0 + lc);
    float4 a1 = *(const float4*)(A + (size_t)(m0+lr+32)*NIN + k0 + lc);
    float4 v0 = *(const float4*)(W + (size_t)(n0+lr   )*NIN + k0 + lc);
    float4 v1 = *(const float4*)(W + (size_t)(n0+lr+32)*NIN + k0 + lc);
    __syncthreads();
    As[lc+0][lr] = a0.x; As[lc+1][lr] = a0.y; As[lc+2][lr] = a0.z; As[lc+3][lr] = a0.w;
    As[lc+0][lr+32] = a1.x; As[lc+1][lr+32] = a1.y; As[lc+2][lr+32] = a1.z; As[lc+3][lr+32] = a1.w;
    Bs[lc+0][lr] = v0.x; Bs[lc+1][lr] = v0.y; Bs[lc+2][lr] = v0.z; Bs[lc+3][lr] = v0.w;
    Bs[lc+0][lr+32] = v1.x; Bs[lc+1][lr+32] = v1.y; Bs[lc+2][lr+32] = v1.z; Bs[lc+3][lr+32] = v1.w;
    __syncthreads();
    #pragma unroll
    for (int kk = 0; kk < 32; kk++) {
      float4 av = *(const float4*)(&As[kk][ty*4]);
      ulonglong2 bp = *(const ulonglong2*)(&Bs[kk][tx*4]);
      u64 d0, d1, d2, d3;
      DUP2(d0, av.x); DUP2(d1, av.y); DUP2(d2, av.z); DUP2(d3, av.w);
      FMA2(acc2[0][0], d0, bp.x); FMA2(acc2[0][1], d0, bp.y);
      FMA2(acc2[1][0], d1, bp.x); FMA2(acc2[1][1], d1, bp.y);
      FMA2(acc2[2][0], d2, bp.x); FMA2(acc2[2][1], d2, bp.y);
      FMA2(acc2[3][0], d3, bp.x); FMA2(acc2[3][1], d3, bp.y);
    }
  }

  float4 bv = *(const float4*)(bias + n0 + tx*4);
  #pragma unroll
  for (int i = 0; i < 4; i++) {
    int row = m0 + ty*4 + i;
    float c0, c1, c2, c3;
    UNPACK2(c0, c1, acc2[i][0]);
    UNPACK2(c2, c3, acc2[i][1]);
    float4 o;
    o.x = c0 + bv.x; o.y = c1 + bv.y;
    o.z = c2 + bv.z; o.w = c3 + bv.w;
    *(float4*)(C + (size_t)row*NH + n0 + tx*4) = o;
  }
}

// ---- persistent GRU recurrence: 2 interleaved chains, single-dump reduce ----
// 128 CTAs = 16 j-tiles x 8 CTA-rows (m). CTA (m, jt) runs chains gA=2m, gB=2m+1
// (4 batches each) over cols [jt*32,+32), weights smem-resident. Phases are fully
// sequential per chain (wait -> stage -> matvec -> dump -> reduce/epilogue) so chain
// A's handshake hides behind chain B's compute. Epilogue duty split: chain A ->
// warps 12..15, chain B -> warps 8..11 (one epilogue max per warp per step).
// 544 threads: warps 0..15 workers (k-split 16), warp 16 = L2 flag poller.
__global__ void __launch_bounds__(544, 1) gru_rec(
    const float* __restrict__ h0,
    const float* __restrict__ w_hr, const float* __restrict__ w_hz, const float* __restrict__ w_hn,
    const float* __restrict__ b_hr, const float* __restrict__ b_hz, const float* __restrict__ b_hn,
    float* __restrict__ out, int write_hlast)
{
  extern __shared__ float sm[];
  float* wsm  = sm + WS_OFF;                 // [3][32][512], float4-XOR swizzled
  float* hsm  = sm + HS_OFF;                 // [4][512] (shared by both phases; warp-private cols)
  float* part = sm + PT_OFF;                 // [16][384]
  unsigned* done = (unsigned*)(sm + DONE_OFF);  // [2 chains][16]

  int tid  = threadIdx.x;
  int r    = tid >> 5;                 // 0..15 worker k-split; 16 = poller
  int jl   = tid & 31;
  int m    = blockIdx.x >> 4;          // 0..7
  int jt   = blockIdx.x & 15;
  int j    = jt*32 + jl;
  int k0   = r*32;
  int sw   = (jl & 7);                 // float4 swizzle key

  if (tid < 512) {
    const float* srcs[3] = {w_hr, w_hz, w_hn};
    #pragma unroll
    for (int g = 0; g < 3; g++) {
      const float* wsrc = srcs[g] + (size_t)j*NH;
      float* wdst = wsm + (g*32 + jl)*512;
      #pragma unroll
      for (int kk = 0; kk < 32; kk += 4) {
        int k16 = (k0 + kk) >> 2;
        *(float4*)(wdst + ((k16 ^ sw) << 2)) = *(const float4*)(wsrc + k0 + kk);
      }
    }
  }
  if (tid < 32) done[tid] = 0u;
  __syncthreads();

  // ---- poller warp: 32 lanes <-> 32 flags (this CTA-row's two groups) ----
  if (r == 16) {
    if (jl < 32) {
      const unsigned* fp = g_flags + m*32 + jl;
      unsigned* dp = done + jl;
      unsigned last = 0u;
      while (last < (unsigned)NSTEP) {
        unsigned v = ld_acq(fp);
        if (v > last) { last = v; st_rel_sh(dp, v); }
      }
    }
    return;
  }

  // ---- workers ----
  float bhr = b_hr[j], bhz = b_hz[j], bhn = b_hn[j];

  const float* wr = wsm + (0*32 + jl)*512;
  const float* wz = wsm + (1*32 + jl)*512;
  const float* wn = wsm + (2*32 + jl)*512;

  // epilogue role: chain A -> warps 12..15, chain B -> warps 8..11
  int myc = -1, eb = 0;
  if (r >= 12)      { myc = 0; eb = r - 12; }
  else if (r >= 8)  { myc = 1; eb = r - 8;  }

  float hprev = 0.f;
  const float *xp0 = 0, *xp1 = 0, *xp2 = 0;
  float *outp = 0, *hlastp = 0;
  unsigned* flagp = 0;
  int ebb = 0;
  if (myc >= 0) {
    ebb = (2*m + myc)*4 + eb;
    hprev = h0[(size_t)ebb*NH + j];
    xp0 = g_x + (size_t)ebb*NSTEP*NH + j;
    xp1 = xp0 + (size_t)NBATCH*NSTEP*NH;
    xp2 = xp1 + (size_t)NBATCH*NSTEP*NH;
    outp = out + (size_t)ebb*NSTEP*NH + j;
    hlastp = out + (size_t)NBATCH*NSTEP*NH + (size_t)ebb*NH + j;
    flagp = g_flags + m*32 + myc*16 + jt;
  }
  int et = eb*32 + jl;                 // 0..127 epilogue column index

  // staging map: warp r stages chunk h[4b][k0..+32) = 32 float4, 1 per lane
  int sb = jl >> 3, sc = jl & 7;
  int sidx = sb*128 + r*8 + sc;

  #pragma unroll 1
  for (int t = 0; t < NSTEP; t++) {
    // prefetch my chain's x contributions (DRAM, consumed in my epilogue)
    float xr = 0.f, xz = 0.f, xn = 0.f;
    if (myc >= 0) {
      xr = __ldcs(xp0 + (size_t)t*NH);
      xz = __ldcs(xp1 + (size_t)t*NH);
      xn = __ldcs(xp2 + (size_t)t*NH);
    }

    #pragma unroll
    for (int c = 0; c < 2; c++) {
      // per-warp wait on local done flag for my chunk of this chain
      if (t > 0) {
        const unsigned* dp = done + c*16 + r;
        while (ld_acq_sh(dp) < (unsigned)t) { }
      }

      // stage my chunk (warp-private columns; safe to overwrite across phases)
      {
        const float4* src = (t == 0)
          ? (const float4*)(h0 + (size_t)(2*m + c)*4*NH)
          : (const float4*)(g_h + (size_t)((t-1)&1)*NBATCH*NH + (size_t)(2*m + c)*4*NH);
        ((float4*)hsm)[sidx] = __ldcg(src + sidx);
      }
      __syncwarp();

      // matvec: k in [k0, k0+32), 3 gates, 4 batches, packed fp32x2
      u64 ar2[4] = {}, az2[4] = {}, an2[4] = {};
      #pragma unroll
      for (int kk8 = 0; kk8 < 8; kk8++) {
        int s4 = ((r*8 + kk8) ^ sw) << 2;
        int k  = k0 + kk8*4;
        ulonglong2 vr = *(const ulonglong2*)(wr + s4);
        ulonglong2 vz = *(const ulonglong2*)(wz + s4);
        ulonglong2 vn = *(const ulonglong2*)(wn + s4);
        #pragma unroll
        for (int b = 0; b < 4; b++) {
          ulonglong2 hv = *(const ulonglong2*)(hsm + b*NH + k);
          FMA2(ar2[b], vr.x, hv.x); FMA2(ar2[b], vr.y, hv.y);
          FMA2(az2[b], vz.x, hv.x); FMA2(az2[b], vz.y, hv.y);
          FMA2(an2[b], vn.x, hv.x); FMA2(an2[b], vn.y, hv.y);
        }
      }
      float sr[4], sz[4], sn[4];
      #pragma unroll
      for (int b = 0; b < 4; b++) {
        float lo, hi;
        UNPACK2(lo, hi, ar2[b]); sr[b] = lo + hi;
        UNPACK2(lo, hi, az2[b]); sz[b] = lo + hi;
        UNPACK2(lo, hi, an2[b]); sn[b] = lo + hi;
      }

      // part free: previous phase's epilogue has finished reading (it rendezvouses here)
      asm volatile("bar.sync 1, 512;" ::: "memory");

      {
        int row = r*384;
        #pragma unroll
        for (int b = 0; b < 4; b++) {
          part[row +   0 + b*32 + jl] = sr[b];
          part[row + 128 + b*32 + jl] = sz[b];
          part[row + 256 + b*32 + jl] = sn[b];
        }
      }
      asm volatile("bar.sync 1, 512;" ::: "memory");

      // epilogue: only this chain's 4 dedicated warps
      if (myc == c) {
        float Sr = 0.f, Sz = 0.f, Sn = 0.f;
        #pragma unroll
        for (int rr = 0; rr < 16; rr++) {
          Sr += part[rr*384 +       et];
          Sz += part[rr*384 + 128 + et];
          Sn += part[rr*384 + 256 + et];
        }
        float rg = 1.f/(1.f + __expf(-(xr + Sr + bhr)));
        float zg = 1.f/(1.f + __expf(-(xz + Sz + bhz)));
        float ng = tanhf(xn + rg*(Sn + bhn));
        float hnew = (1.f - zg)*ng + zg*hprev;
        hprev = hnew;

        __stcg(&g_h[(size_t)(t&1)*NBATCH*NH + (size_t)ebb*NH + j], hnew);

        // 128-thread rendezvous among this chain's epilogue warps, then release
        if (c == 0) asm volatile("bar.sync 2, 128;" ::: "memory");
        else        asm volatile("bar.sync 3, 128;" ::: "memory");
        if (eb == 0 && jl == 0) {
          st_rel(flagp, (unsigned)(t+1));
          st_rel_sh(done + c*16 + jt, (unsigned)(t+1));  // self-publish
        }

        // non-critical stores after the release
        __stcs(outp + (size_t)t*NH, hnew);
        if (write_hlast && t == NSTEP-1) hlastp[0] = hnew;
      }
    }
  }
}

extern "C" void kernel_launch(void* const* d_in, const int* in_sizes, int n_in,
                              void* d_out, int out_size) {
  const float* inp  = (const float*)d_in[0];
  const float* h0   = (const float*)d_in[1];
  const float* w_ir = (const float*)d_in[2];
  const float* w_iz = (const float*)d_in[3];
  const float* w_in = (const float*)d_in[4];
  const float* b_ir = (const float*)d_in[5];
  const float* b_iz = (const float*)d_in[6];
  const float* b_in = (const float*)d_in[7];
  const float* w_hr = (const float*)d_in[8];
  const float* w_hz = (const float*)d_in[9];
  const float* w_hn = (const float*)d_in[10];
  const float* b_hr = (const float*)d_in[11];
  const float* b_hz = (const float*)d_in[12];
  const float* b_hn = (const float*)d_in[13];
  float* out = (float*)d_out;

  cudaFuncSetAttribute(gru_rec, cudaFuncAttributeMaxDynamicSharedMemorySize, SMEM_BYTES);

  dim3 gg(NH/64, (NBATCH*NSTEP)/64, 3);
  xproj_kernel<<<gg, 256>>>(inp, w_ir, w_iz, w_in, b_ir, b_iz, b_in);

  int write_hlast = (out_size >= NBATCH*NSTEP*NH + NBATCH*NH) ? 1 : 0;
  gru_rec<<<128, 544, SMEM_BYTES>>>(h0, w_hr, w_hz, w_hn, b_hr, b_hz, b_hn,
                                    out, write_hlast);
}